// round 17
// baseline (speedup 1.0000x reference)
#include <cuda_runtime.h>
#include <cuda_bf16.h>
#include <cuda_fp16.h>
#include <cstdint>
#include <math.h>

#define D_MODEL 2048
#define NH 16
#define DH 128
#define BB 2
#define SS 2048
#define MTOT (BB*SS)      /* 4096 */
#define NPROJ (NH*DH)     /* 2048 */
/* 1/sqrt(128) * log2(e): S computed in log2 domain -> exp2f */
#define QK_SCALE 0.12753100293214864f

// ---------------- scratch ----------------
__device__ __half g_x16[(size_t)MTOT*D_MODEL];         // x, fp16
__device__ __half g_wq16[(size_t)D_MODEL*NPROJ];       // W^T [N][K], fp16
__device__ __half g_wk16[(size_t)D_MODEL*NPROJ];
__device__ __half g_wv16[(size_t)D_MODEL*NPROJ];
__device__ __half g_wo16[(size_t)D_MODEL*NPROJ];
__device__ __half g_c16[(size_t)MTOT*NPROJ];           // ctx fp16 [b,s,h*128+d]
__device__ float g_qt[(size_t)BB*NH*SS*DH];            // Q, tf32-rounded (scaled)
__device__ float g_kt[(size_t)BB*NH*SS*DH];            // K, tf32-rounded
__device__ __half g_v16[(size_t)BB*NH*DH*SS];          // V fp16, transposed [b,h,d,s]

// ---------------- helpers ----------------
__device__ __forceinline__ uint32_t smem_u32(const void* p) {
    uint32_t a;
    asm("{ .reg .u64 t; cvta.to.shared.u64 t, %1; cvt.u32.u64 %0, t; }" : "=r"(a) : "l"(p));
    return a;
}
#define CP_ASYNC16(dst, src) \
    asm volatile("cp.async.cg.shared.global [%0], [%1], 16;" :: "r"(dst), "l"(src))
#define CP_COMMIT() asm volatile("cp.async.commit_group;" ::: "memory")
#define CP_WAIT1() asm volatile("cp.async.wait_group 1;" ::: "memory")
#define CP_WAIT0() asm volatile("cp.async.wait_group 0;" ::: "memory")

__device__ __forceinline__ void mma_f16(float* c, const uint32_t* a,
                                        uint32_t b0, uint32_t b1) {
    asm volatile(
        "mma.sync.aligned.m16n8k16.row.col.f32.f16.f16.f32 "
        "{%0,%1,%2,%3}, {%4,%5,%6,%7}, {%8,%9}, {%0,%1,%2,%3};"
        : "+f"(c[0]), "+f"(c[1]), "+f"(c[2]), "+f"(c[3])
        : "r"(a[0]), "r"(a[1]), "r"(a[2]), "r"(a[3]), "r"(b0), "r"(b1));
}
__device__ __forceinline__ void mma_tf32(float* c, const uint32_t* a,
                                         uint32_t b0, uint32_t b1) {
    asm volatile(
        "mma.sync.aligned.m16n8k8.row.col.f32.tf32.tf32.f32 "
        "{%0,%1,%2,%3}, {%4,%5,%6,%7}, {%8,%9}, {%0,%1,%2,%3};"
        : "+f"(c[0]), "+f"(c[1]), "+f"(c[2]), "+f"(c[3])
        : "r"(a[0]), "r"(a[1]), "r"(a[2]), "r"(a[3]), "r"(b0), "r"(b1));
}
__device__ __forceinline__ void ldsmx4(uint32_t* r, uint32_t addr) {
    asm volatile("ldmatrix.sync.aligned.m8n8.x4.shared.b16 {%0,%1,%2,%3}, [%4];"
                 : "=r"(r[0]), "=r"(r[1]), "=r"(r[2]), "=r"(r[3]) : "r"(addr));
}
__device__ __forceinline__ uint32_t pack_f16x2(float lo, float hi) {
    uint32_t r;
    asm("cvt.rn.f16x2.f32 %0, %1, %2;" : "=r"(r) : "f"(hi), "f"(lo));
    return r;
}
__device__ __forceinline__ void split2h(float x, float y, uint32_t& h2, uint32_t& l2) {
    float xh = __half2float(__float2half_rn(x));
    float yh = __half2float(__float2half_rn(y));
    h2 = pack_f16x2(xh, yh);
    l2 = pack_f16x2(x - xh, y - yh);
}
__device__ __forceinline__ float tf32r(float x) {
    uint32_t y;
    asm("cvt.rna.tf32.f32 %0, %1;" : "=r"(y) : "f"(x));
    return __uint_as_float(y);
}

// ---------------- conversion kernels ----------------
__global__ void __launch_bounds__(256) cvt_f16(const float* __restrict__ src,
                                               __half* __restrict__ dst, int n4)
{
    int i = blockIdx.x * 256 + threadIdx.x;
    if (i >= n4) return;
    float4 v = ((const float4*)src)[i];
    uint2 o;
    o.x = pack_f16x2(v.x, v.y);
    o.y = pack_f16x2(v.z, v.w);
    ((uint2*)dst)[i] = o;
}

// 4 weights W[K][N] -> Wt [N][K] fp16, fused via blockIdx.z
__global__ void __launch_bounds__(256) transcvt4(
    const float* __restrict__ W0, const float* __restrict__ W1,
    const float* __restrict__ W2, const float* __restrict__ W3,
    __half* __restrict__ t0, __half* __restrict__ t1,
    __half* __restrict__ t2, __half* __restrict__ t3)
{
    const float* W; __half* to;
    switch (blockIdx.z) {
        case 0: W = W0; to = t0; break;
        case 1: W = W1; to = t1; break;
        case 2: W = W2; to = t2; break;
        default: W = W3; to = t3; break;
    }
    __shared__ float tile[32][33];
    int nb = blockIdx.x * 32, kb = blockIdx.y * 32;
    int tx = threadIdx.x & 31, ty = threadIdx.x >> 5;
#pragma unroll
    for (int j = 0; j < 4; j++)
        tile[ty + j*8][tx] = W[(size_t)(kb + ty + j*8) * D_MODEL + nb + tx];
    __syncthreads();
#pragma unroll
    for (int j = 0; j < 4; j++) {
        int n = nb + ty + j*8;
        to[(size_t)n * D_MODEL + kb + tx] = __float2half_rn(tile[tx][ty + j*8]);
    }
}

// ---------------- FP16 GEMM core: 128x128, Kt=64 fp16, 256 thr, 96KB ------
#define FOFF_A 0
#define FOFF_B 16384
#define FBUF 32768
#define GEMM_SMEM (3*FBUF)
// epilogue staging (reuses GEMM smem after mainloop)
#define EPLD 136       /* f16 path: 136 halfs per row */
#define EPLDF 132      /* fp32 path: 132 floats per row */

__device__ __forceinline__ void f_issue(const __half* A, const __half* B,
                                        uint32_t sb, int bm, int bn, int K, int t,
                                        int it, int buf)
{
    const size_t koff = (size_t)it * 64;
    const uint32_t bb = sb + buf * FBUF;
#pragma unroll
    for (int i = 0; i < 4; i++) {
        int id = t + i * 256;
        int r = id >> 3, c = id & 7;           // 128 rows x 8 chunks(16B)
        uint32_t sw = ((uint32_t)r << 7) + ((uint32_t)(c ^ (r & 7)) << 4);
        CP_ASYNC16(bb + FOFF_A + sw, A + (size_t)(bm + r) * K + koff + c * 8);
        CP_ASYNC16(bb + FOFF_B + sw, B + (size_t)(bn + r) * K + koff + c * 8);
    }
}

// warp grid 2(M) x 4(N); warp tile 64M x 32N
__device__ __forceinline__ void gemm_core_f16(const __half* A, const __half* B,
                                              uint32_t sb, int bm, int bn, int K,
                                              int t, int lane, int warp_m, int warp_n,
                                              float acc[4][4][4])
{
    const int q8 = lane >> 3, rr = lane & 7;
    const int chqA = q8 >> 1, chqB = q8 & 1;
    int rA128[4], mA[4], rB128[2], mB[2];
#pragma unroll
    for (int mf = 0; mf < 4; mf++) {
        int r = warp_m * 64 + mf * 16 + rr + ((q8 & 1) << 3);
        rA128[mf] = r << 7; mA[mf] = r & 7;
    }
#pragma unroll
    for (int p = 0; p < 2; p++) {
        int r = warp_n * 32 + p * 16 + rr + ((q8 >> 1) << 3);
        rB128[p] = r << 7; mB[p] = r & 7;
    }

    const int iters = K >> 6;                  // Kt = 64
    f_issue(A, B, sb, bm, bn, K, t, 0, 0); CP_COMMIT();
    f_issue(A, B, sb, bm, bn, K, t, 1, 1); CP_COMMIT();

    int buf = 0;
    for (int it = 0; it < iters; it++) {
        if (it == iters - 1) { CP_WAIT0(); } else { CP_WAIT1(); }
        __syncthreads();
        if (it + 2 < iters) {
            int b2 = buf + 2; if (b2 >= 3) b2 -= 3;
            f_issue(A, B, sb, bm, bn, K, t, it + 2, b2);
            CP_COMMIT();
        }
        const uint32_t cb = sb + buf * FBUF;
#pragma unroll
        for (int ks = 0; ks < 4; ks++) {       // 4 k16-steps per ktile
            const int ch0 = ks * 2;
            uint32_t aq[4][4], b4[2][4];
#pragma unroll
            for (int mf = 0; mf < 4; mf++)
                ldsmx4(aq[mf], cb + FOFF_A + rA128[mf] + (((ch0 + chqA) ^ mA[mf]) << 4));
#pragma unroll
            for (int p = 0; p < 2; p++)
                ldsmx4(b4[p], cb + FOFF_B + rB128[p] + (((ch0 + chqB) ^ mB[p]) << 4));
#pragma unroll
            for (int mf = 0; mf < 4; mf++)
#pragma unroll
                for (int nf = 0; nf < 4; nf++) {
                    const int p = nf >> 1, h = (nf & 1) * 2;
                    mma_f16(acc[mf][nf], aq[mf], b4[p][h], b4[p][h+1]);
                }
        }
        if (++buf == 3) buf = 0;
    }
}

// fused QKV projections: grid (N/128, M/128, 3)
// z<2: fp32 tf32-rounded out (Q scaled by log2e/sqrt(DH)); z==2: fp16 transposed
__global__ void __launch_bounds__(256, 2) gemm_qkv(
    const __half* __restrict__ x16,
    const __half* __restrict__ wq16, const __half* __restrict__ wk16,
    const __half* __restrict__ wv16,
    const float* __restrict__ bq, const float* __restrict__ bk, const float* __restrict__ bv,
    float* __restrict__ qt, float* __restrict__ kt,
    __half* __restrict__ v16)
{
    extern __shared__ char smb[];
    const uint32_t sb = smem_u32(smb);
    const int t = threadIdx.x, lane = t & 31, wid = t >> 5;
    const int g = lane >> 2, tid4 = lane & 3;
    const int warp_m = wid >> 2, warp_n = wid & 3;
    const int bm = blockIdx.y * 128, bn = blockIdx.x * 128;
    const int z = blockIdx.z;

    const __half* B_; const float* bias_;
    if (z == 0)      { B_ = wq16; bias_ = bq; }
    else if (z == 1) { B_ = wk16; bias_ = bk; }
    else             { B_ = wv16; bias_ = bv; }
    const float oscale = (z == 0) ? QK_SCALE : 1.0f;

    float acc[4][4][4];
#pragma unroll
    for (int a = 0; a < 4; a++)
#pragma unroll
        for (int b = 0; b < 4; b++)
#pragma unroll
            for (int c = 0; c < 4; c++) acc[a][b][c] = 0.f;

    gemm_core_f16(x16, B_, sb, bm, bn, D_MODEL, t, lane, warp_m, warp_n, acc);

    __syncthreads();   // mainloop smem reads done before reuse
    float* smf = (float*)smb;
#pragma unroll
    for (int nf = 0; nf < 4; nf++) {
        const int n = warp_n * 32 + nf * 8 + tid4 * 2;   // local n
        const float2 bv2 = *(const float2*)(bias_ + bn + n);
#pragma unroll
        for (int mf = 0; mf < 4; mf++) {
#pragma unroll
            for (int half = 0; half < 2; half++) {
                const int m = warp_m * 64 + mf * 16 + g + half * 8;  // local m
                float wx = (acc[mf][nf][half*2 + 0] + bv2.x) * oscale;
                float wy = (acc[mf][nf][half*2 + 1] + bv2.y) * oscale;
                if (z < 2) {   // fp32 [m][n], tf32-rounded
                    smf[m * EPLDF + n]     = tf32r(wx);
                    smf[m * EPLDF + n + 1] = tf32r(wy);
                } else {       // fp16 transpose [n][m]
                    *(uint16_t*)(smb + (n * EPLD + m) * 2) =
                        (uint16_t)__half_as_ushort(__float2half_rn(wx));
                    *(uint16_t*)(smb + ((n + 1) * EPLD + m) * 2) =
                        (uint16_t)__half_as_ushort(__float2half_rn(wy));
                }
            }
        }
    }
    __syncthreads();

    const int r = t >> 1, part = t & 1;
    if (z < 2) {
        float* O_ = (z == 0) ? qt : kt;
        int m_g = bm + r;
        int b = m_g >> 11, s = m_g & (SS - 1), h = bn >> 7;
        size_t gbase = (((size_t)(b * NH + h)) * SS + s) * DH + part * 64;
        const float* src = smf + r * EPLDF + part * 64;
#pragma unroll
        for (int i = 0; i < 16; i++)
            *(uint4*)(O_ + gbase + i * 4) = *(const uint4*)(src + i * 4);
    } else {
        int b = bm >> 11, s0 = bm & (SS - 1), h = bn >> 7;
        size_t gbase = (((size_t)(b * NH + h)) * DH + r) * SS + s0 + part * 64;
        const uint32_t so = (uint32_t)(r * EPLD + part * 64) * 2;
#pragma unroll
        for (int i = 0; i < 8; i++)
            *(uint4*)(v16 + gbase + i * 8) = *(const uint4*)(smb + so + i * 16);
    }
}

// output projection: ctx fp16 @ Wo fp16 -> fp32 row-major out
__global__ void __launch_bounds__(256, 2) gemm_out(
    const __half* __restrict__ A16, const __half* __restrict__ B16,
    const float* __restrict__ bias, float* __restrict__ Cf)
{
    extern __shared__ char smb[];
    const uint32_t sb = smem_u32(smb);
    const int t = threadIdx.x, lane = t & 31, wid = t >> 5;
    const int g = lane >> 2, tid4 = lane & 3;
    const int warp_m = wid >> 2, warp_n = wid & 3;
    const int bm = blockIdx.y * 128, bn = blockIdx.x * 128;

    float acc[4][4][4];
#pragma unroll
    for (int a = 0; a < 4; a++)
#pragma unroll
        for (int b = 0; b < 4; b++)
#pragma unroll
            for (int c = 0; c < 4; c++) acc[a][b][c] = 0.f;

    gemm_core_f16(A16, B16, sb, bm, bn, D_MODEL, t, lane, warp_m, warp_n, acc);

#pragma unroll
    for (int nf = 0; nf < 4; nf++) {
        const int n = bn + warp_n * 32 + nf * 8 + tid4 * 2;
        const float2 bv2 = *(const float2*)(bias + n);
#pragma unroll
        for (int mf = 0; mf < 4; mf++) {
#pragma unroll
            for (int half = 0; half < 2; half++) {
                const int m = bm + warp_m * 64 + mf * 16 + g + half * 8;
                float2 w;
                w.x = acc[mf][nf][half*2 + 0] + bv2.x;
                w.y = acc[mf][nf][half*2 + 1] + bv2.y;
                *(float2*)(Cf + (size_t)m * D_MODEL + n) = w;
            }
        }
    }
}

// ---------------- Flash: tf32 S, fp16x2 PV, no-max exp2 softmax ------
#define FQ 0
#define FK 32768
#define FV 65536
#define FA_SMEM 81920

__device__ __forceinline__ uint32_t sw512(int r, int ch) {   // fp32 row = 512B
    return (uint32_t)(r * 512 + ((ch ^ (r & 7)) << 4));
}
__device__ __forceinline__ uint32_t sw128(int r, int byteoff) {
    int c = byteoff >> 4;
    int sc = c ^ (r & 7);
    return (uint32_t)(r * 128 + sc * 16 + (byteoff & 15));
}

__global__ void __launch_bounds__(128) flash_mma(
    const float* __restrict__ Qt, const float* __restrict__ Kt,
    const __half* __restrict__ V16,
    __half* __restrict__ C16)
{
    extern __shared__ char smb[];
    const uint32_t sb = smem_u32(smb);
    const int t = threadIdx.x;
    const int lane = t & 31, w = t >> 5;
    const int g = lane >> 2, t4 = lane & 3;
    const int qi = gridDim.x - 1 - blockIdx.x;   // heavy tiles first
    const int bh = blockIdx.y;
    const size_t hb = (size_t)bh * SS * DH;

    const int q8 = lane >> 3, rr = lane & 7;
    const int rowh = (q8 & 1) << 3, kh = q8 >> 1;
    const int rQ = w * 16 + rr + rowh;
    const int rQ512 = rQ * 512, mQ = rQ & 7;
    int rK512[4], mK[4];
#pragma unroll
    for (int p = 0; p < 4; p++) {
        int r = p * 16 + rr + rowh;
        rK512[p] = r * 512; mK[p] = r & 7;
    }
    const int chqB = q8 & 1;
    int rV128[8], mV[8];
#pragma unroll
    for (int p = 0; p < 8; p++) {
        int r = p * 16 + rr + ((q8 >> 1) << 3);
        rV128[p] = r << 7; mV[p] = r & 7;
    }

    auto k_issue = [&](int kj2) {
        const float* kb = Kt + hb + (size_t)kj2 * 64 * DH;
#pragma unroll
        for (int i = 0; i < 16; i++) {
            int id = t + i * 128;
            int r = id >> 5, c = id & 31;
            CP_ASYNC16(sb + FK + sw512(r, c), kb + (size_t)r * DH + c * 4);
        }
    };
    auto v_issue = [&](int kj2) {
        const __half* vb = V16 + hb + (size_t)kj2 * 64;
#pragma unroll
        for (int i = 0; i < 8; i++) {
            int id = t + i * 128;
            int r = id >> 3, c = id & 7;
            CP_ASYNC16(sb + FV + sw128(r, c * 16), vb + (size_t)r * SS + c * 8);
        }
    };

    {
        const float* qb = Qt + hb + (size_t)qi * 64 * DH;
#pragma unroll
        for (int i = 0; i < 16; i++) {
            int id = t + i * 128;
            int r = id >> 5, c = id & 31;
            CP_ASYNC16(sb + FQ + sw512(r, c), qb + (size_t)r * DH + c * 4);
        }
    }
    CP_COMMIT();
    k_issue(0); CP_COMMIT();
    v_issue(0); CP_COMMIT();

    float o[16][4];
#pragma unroll
    for (int i = 0; i < 16; i++)
#pragma unroll
        for (int j = 0; j < 4; j++) o[i][j] = 0.f;
    float l0p = 0.f, l1p = 0.f;

    const int qr0 = w * 16 + g;

    for (int kj = 0; kj <= qi; kj++) {
        CP_WAIT1();
        __syncthreads();

        // ---- S = Q K^T (tf32; overlaps with V(kj) load) ----
        float s[8][4];
#pragma unroll
        for (int nt = 0; nt < 8; nt++)
#pragma unroll
            for (int j = 0; j < 4; j++) s[nt][j] = 0.f;

#pragma unroll
        for (int kk = 0; kk < 16; kk++) {
            const int cc = 2 * kk + kh;
            uint32_t aq[4];
            ldsmx4(aq, sb + FQ + rQ512 + ((cc ^ mQ) << 4));
#pragma unroll
            for (int p = 0; p < 4; p++) {
                uint32_t kb4[4];
                ldsmx4(kb4, sb + FK + rK512[p] + ((cc ^ mK[p]) << 4));
                mma_tf32(s[2*p],     aq, kb4[0], kb4[2]);
                mma_tf32(s[2*p + 1], aq, kb4[1], kb4[3]);
            }
        }
        __syncthreads();
        if (kj < qi) { k_issue(kj + 1); CP_COMMIT(); }

        // ---- causal mask + no-max softmax (log2 domain) ----
        if (kj == qi) {
#pragma unroll
            for (int nt = 0; nt < 8; nt++) {
                int c0 = nt * 8 + 2 * t4;
                if (c0     > qr0)     s[nt][0] = -1e30f;
                if (c0 + 1 > qr0)     s[nt][1] = -1e30f;
                if (c0     > qr0 + 8) s[nt][2] = -1e30f;
                if (c0 + 1 > qr0 + 8) s[nt][3] = -1e30f;
            }
        }
#pragma unroll
        for (int nt = 0; nt < 8; nt++) {
            s[nt][0] = exp2f(s[nt][0]);
            s[nt][1] = exp2f(s[nt][1]);
            s[nt][2] = exp2f(s[nt][2]);
            s[nt][3] = exp2f(s[nt][3]);
            l0p += s[nt][0] + s[nt][1];
            l1p += s[nt][2] + s[nt][3];
        }

        if (kj < qi) { CP_WAIT1(); } else { CP_WAIT0(); }
        __syncthreads();

        // ---- PV: (Ph + Pl) * V  (fp16, 2 passes) ----
#pragma unroll
        for (int kt = 0; kt < 4; kt++) {
            uint32_t aph[4], apl[4];
            split2h(s[2*kt][0],   s[2*kt][1],   aph[0], apl[0]);
            split2h(s[2*kt][2],   s[2*kt][3],   aph[1], apl[1]);
            split2h(s[2*kt+1][0], s[2*kt+1][1], aph[2], apl[2]);
            split2h(s[2*kt+1][2], s[2*kt+1][3], aph[3], apl[3]);
#pragma unroll
            for (int p = 0; p < 8; p++) {
                uint32_t vh4[4];
                ldsmx4(vh4, sb + FV + rV128[p] + ((kt*2 + chqB) ^ mV[p]) * 16);
                mma_f16(o[2*p],   aph, vh4[0], vh4[1]);
                mma_f16(o[2*p],   apl, vh4[0], vh4[1]);
                mma_f16(o[2*p+1], aph, vh4[2], vh4[3]);
                mma_f16(o[2*p+1], apl, vh4[2], vh4[3]);
            }
        }
        __syncthreads();
        if (kj < qi) { v_issue(kj + 1); CP_COMMIT(); }
    }

    // ---- final row-sum reduction ----
    l0p += __shfl_xor_sync(0xffffffff, l0p, 1);
    l0p += __shfl_xor_sync(0xffffffff, l0p, 2);
    l1p += __shfl_xor_sync(0xffffffff, l1p, 1);
    l1p += __shfl_xor_sync(0xffffffff, l1p, 2);

    // ---- epilogue: normalize, store fp16 ctx [b,s, h*128+d] ----
    const float inv0 = 1.f / l0p, inv1 = 1.f / l1p;
    const int b = bh >> 4, h = bh & 15;
    const int row0 = qi * 64 + qr0;
#pragma unroll
    for (int ntc = 0; ntc < 16; ntc++) {
        const int col = h * 128 + ntc * 8 + 2 * t4;
        size_t i0 = ((size_t)(b * SS + row0)) * NPROJ + col;
        size_t i1 = ((size_t)(b * SS + row0 + 8)) * NPROJ + col;
        *(uint32_t*)(C16 + i0) = pack_f16x2(o[ntc][0] * inv0, o[ntc][1] * inv0);
        *(uint32_t*)(C16 + i1) = pack_f16x2(o[ntc][2] * inv1, o[ntc][3] * inv1);
    }
}

// ---------------- launch ----------------
extern "C" void kernel_launch(void* const* d_in, const int* in_sizes, int n_in,
                              void* d_out, int out_size)
{
    const float* x  = (const float*)d_in[0];
    const float* Wq = (const float*)d_in[1];
    const float* bq = (const float*)d_in[2];
    const float* Wk = (const float*)d_in[3];
    const float* bk = (const float*)d_in[4];
    const float* Wv = (const float*)d_in[5];
    const float* bv = (const float*)d_in[6];
    const float* Wo = (const float*)d_in[7];
    const float* bo = (const float*)d_in[8];
    float* out = (float*)d_out;

    __half *x16, *wq16, *wk16, *wv16, *wo16, *c16, *v16;
    float *qt, *kt;
    cudaGetSymbolAddress((void**)&x16,  g_x16);
    cudaGetSymbolAddress((void**)&wq16, g_wq16);
    cudaGetSymbolAddress((void**)&wk16, g_wk16);
    cudaGetSymbolAddress((void**)&wv16, g_wv16);
    cudaGetSymbolAddress((void**)&wo16, g_wo16);
    cudaGetSymbolAddress((void**)&c16,  g_c16);
    cudaGetSymbolAddress((void**)&v16,  g_v16);
    cudaGetSymbolAddress((void**)&qt,   g_qt);
    cudaGetSymbolAddress((void**)&kt,   g_kt);

    cudaFuncSetAttribute(gemm_qkv, cudaFuncAttributeMaxDynamicSharedMemorySize, GEMM_SMEM);
    cudaFuncSetAttribute(gemm_out, cudaFuncAttributeMaxDynamicSharedMemorySize, GEMM_SMEM);
    cudaFuncSetAttribute(flash_mma, cudaFuncAttributeMaxDynamicSharedMemorySize, FA_SMEM);

    const int n4x = (MTOT * D_MODEL) / 4;
    cvt_f16<<<(n4x + 255) / 256, 256>>>(x, x16, n4x);
    dim3 tgrid(D_MODEL / 32, D_MODEL / 32, 4);
    transcvt4<<<tgrid, 256>>>(Wq, Wk, Wv, Wo, wq16, wk16, wv16, wo16);

    dim3 qkvgrid(NPROJ / 128, MTOT / 128, 3);   // (16, 32, 3)
    gemm_qkv<<<qkvgrid, 256, GEMM_SMEM>>>(x16, wq16, wk16, wv16,
                                          bq, bk, bv, qt, kt, v16);

    dim3 fgrid(SS / 64, BB * NH);               // (32, 32)
    flash_mma<<<fgrid, 128, FA_SMEM>>>(qt, kt, v16, c16);

    dim3 ogrid(NPROJ / 128, MTOT / 128);        // (16, 32)
    gemm_out<<<ogrid, 256, GEMM_SMEM>>>(c16, wo16, bo, out);
}